// round 1
// baseline (speedup 1.0000x reference)
#include <cuda_runtime.h>
#include <math.h>

#define NN 50000
#define NE 800000
#define F  128

// ---------------- scratch (device globals; no allocation allowed) ----------------
__device__ int   g_outdeg[NN];
__device__ int   g_indeg[NN];
__device__ __align__(16) float g_srcnorm[NN];
__device__ __align__(16) float g_dstnorm[NN];
__device__ int   g_offsets[NN + 1];
__device__ int   g_cursor[NN];
__device__ int   g_csrsrc[NE];
__device__ int   g_blksums[64];
__device__ int   g_blkoffs[64];
__device__ __align__(16) float g_x0[(size_t)NN * F];
__device__ __align__(16) float g_x1[(size_t)NN * F];
__device__ __align__(16) float g_x2[(size_t)NN * F];
__device__ __align__(16) float g_y [(size_t)NN * 64];

// ---------------- preprocessing: degrees, norms, CSR-by-dst ----------------
__global__ void k_zero(int n) {
    int i = blockIdx.x * blockDim.x + threadIdx.x;
    if (i < n) { g_outdeg[i] = 0; g_indeg[i] = 0; }
}

__global__ void k_deg(const int* __restrict__ src, const int* __restrict__ dst, int e) {
    int i = blockIdx.x * blockDim.x + threadIdx.x;
    if (i < e) {
        atomicAdd(&g_outdeg[src[i]], 1);
        atomicAdd(&g_indeg[dst[i]], 1);
    }
}

__global__ void k_norm(int n) {
    int i = blockIdx.x * blockDim.x + threadIdx.x;
    if (i < n) {
        int od = g_outdeg[i];
        int id = g_indeg[i];
        g_srcnorm[i] = od > 0 ? rsqrtf((float)od) : 0.f;
        g_dstnorm[i] = id > 0 ? rsqrtf((float)id) : 0.f;
    }
}

__global__ void k_scan1(int n) {
    __shared__ int sh[1024];
    int tid = threadIdx.x;
    int i = blockIdx.x * 1024 + tid;
    int v = (i < n) ? g_indeg[i] : 0;
    sh[tid] = v;
    __syncthreads();
    for (int off = 1; off < 1024; off <<= 1) {
        int t = (tid >= off) ? sh[tid - off] : 0;
        __syncthreads();
        sh[tid] += t;
        __syncthreads();
    }
    if (i < n) g_offsets[i] = sh[tid] - v;           // exclusive within block
    if (tid == 1023) g_blksums[blockIdx.x] = sh[1023];
}

__global__ void k_scan2(int nb) {
    if (blockIdx.x == 0 && threadIdx.x == 0) {
        int s = 0;
        for (int b = 0; b < nb; b++) { g_blkoffs[b] = s; s += g_blksums[b]; }
    }
}

__global__ void k_scan3(int n, int e) {
    int i = blockIdx.x * blockDim.x + threadIdx.x;
    if (i < n) {
        int o = g_offsets[i] + g_blkoffs[i >> 10];
        g_offsets[i] = o;
        g_cursor[i] = o;
    }
    if (i == 0) g_offsets[n] = e;
}

__global__ void k_scatter(const int* __restrict__ src, const int* __restrict__ dst, int e) {
    int i = blockIdx.x * blockDim.x + threadIdx.x;
    if (i < e) {
        int d = dst[i];
        int pos = atomicAdd(&g_cursor[d], 1);
        g_csrsrc[pos] = src[i];
    }
}

// x0 = features * src_norm[row]
__global__ void k_scale0(const float* __restrict__ feats, int n) {
    int i = blockIdx.x * blockDim.x + threadIdx.x;   // over n * (F/4) float4s
    if (i < n * (F / 4)) {
        int row = i / (F / 4);
        float4 v = ((const float4*)feats)[i];
        float s = g_srcnorm[row];
        v.x *= s; v.y *= s; v.z *= s; v.w *= s;
        ((float4*)g_x0)[i] = v;
    }
}

// ---------------- fused conv layer: gather-SpMM + smem GEMM + relu (+ src_norm fold) ----------------
// persistent blocks, 256 threads, tile = 16 nodes, W (128x128) in dynamic smem.
template<bool FOLD_SRC_NORM>
__global__ void __launch_bounds__(256, 3) k_layer128(
    const float* __restrict__ xs, const float* __restrict__ W,
    const float* __restrict__ bias, float* __restrict__ out,
    int n, int numTiles)
{
    extern __shared__ float sh[];
    float* shW = sh;                 // 128*128 = 16384 floats (64 KB)
    float* shA = sh + F * F;         // 16*128  =  2048 floats (8 KB)
    float* shB = shA + 16 * F;       // 128 floats

    int tid = threadIdx.x;
    for (int i = tid; i < F * F / 4; i += 256)
        ((float4*)shW)[i] = ((const float4*)W)[i];
    if (tid < F / 4)
        ((float4*)shB)[tid] = ((const float4*)bias)[tid];
    __syncthreads();

    int w = tid >> 5, lane = tid & 31;
    int c = lane * 4;

    for (int t = blockIdx.x; t < numTiles; t += gridDim.x) {
        int base = t * 16;

        // --- aggregation: warp handles local nodes w and w+8 ---
        #pragma unroll
        for (int s2 = 0; s2 < 2; s2++) {
            int ml = w + s2 * 8;
            int m = base + ml;
            float4 acc = make_float4(0.f, 0.f, 0.f, 0.f);
            if (m < n) {
                int e = g_offsets[m], end = g_offsets[m + 1];
                const float* xb = xs + (size_t)lane * 4;
                for (; e + 4 <= end; e += 4) {
                    int i0 = g_csrsrc[e], i1 = g_csrsrc[e + 1];
                    int i2 = g_csrsrc[e + 2], i3 = g_csrsrc[e + 3];
                    float4 v0 = *(const float4*)(xb + (size_t)i0 * F);
                    float4 v1 = *(const float4*)(xb + (size_t)i1 * F);
                    float4 v2 = *(const float4*)(xb + (size_t)i2 * F);
                    float4 v3 = *(const float4*)(xb + (size_t)i3 * F);
                    acc.x += (v0.x + v1.x) + (v2.x + v3.x);
                    acc.y += (v0.y + v1.y) + (v2.y + v3.y);
                    acc.z += (v0.z + v1.z) + (v2.z + v3.z);
                    acc.w += (v0.w + v1.w) + (v2.w + v3.w);
                }
                for (; e < end; e++) {
                    int i0 = g_csrsrc[e];
                    float4 v0 = *(const float4*)(xb + (size_t)i0 * F);
                    acc.x += v0.x; acc.y += v0.y; acc.z += v0.z; acc.w += v0.w;
                }
                float dn = g_dstnorm[m];
                acc.x *= dn; acc.y *= dn; acc.z *= dn; acc.w *= dn;
            }
            *(float4*)(shA + ml * F + lane * 4) = acc;
        }
        __syncthreads();

        // --- GEMM: warp w -> local nodes 2w, 2w+1; lane -> cols [c, c+4) ---
        float4 b4 = *(float4*)(shB + c);
        float4 o0 = b4, o1 = b4;
        const float* a0p = shA + (2 * w) * F;
        const float* a1p = a0p + F;
        #pragma unroll 8
        for (int k = 0; k < F; k++) {
            float a0 = a0p[k], a1 = a1p[k];
            float4 wv = *(const float4*)(shW + k * F + c);
            o0.x += a0 * wv.x; o0.y += a0 * wv.y; o0.z += a0 * wv.z; o0.w += a0 * wv.w;
            o1.x += a1 * wv.x; o1.y += a1 * wv.y; o1.z += a1 * wv.z; o1.w += a1 * wv.w;
        }

        int m0 = base + 2 * w;
        if (m0 < n) {
            float sn = FOLD_SRC_NORM ? g_srcnorm[m0] : 1.f;
            o0.x = fmaxf(o0.x, 0.f) * sn; o0.y = fmaxf(o0.y, 0.f) * sn;
            o0.z = fmaxf(o0.z, 0.f) * sn; o0.w = fmaxf(o0.w, 0.f) * sn;
            *(float4*)(out + (size_t)m0 * F + c) = o0;
        }
        if (m0 + 1 < n) {
            float sn = FOLD_SRC_NORM ? g_srcnorm[m0 + 1] : 1.f;
            o1.x = fmaxf(o1.x, 0.f) * sn; o1.y = fmaxf(o1.y, 0.f) * sn;
            o1.z = fmaxf(o1.z, 0.f) * sn; o1.w = fmaxf(o1.w, 0.f) * sn;
            *(float4*)(out + (size_t)(m0 + 1) * F + c) = o1;
        }
        __syncthreads();
    }
}

// ---------------- y = x2s @ W3 (project BEFORE the last SpMM: halves gather width) ----------------
__global__ void __launch_bounds__(256) k_pre3(
    const float* __restrict__ x, const float* __restrict__ W3,
    float* __restrict__ y, int n, int numTiles)
{
    __shared__ float shW[F * 64];   // 32 KB
    __shared__ float shX[16 * F];   // 8 KB
    int tid = threadIdx.x;
    for (int i = tid; i < F * 64 / 4; i += 256)
        ((float4*)shW)[i] = ((const float4*)W3)[i];
    __syncthreads();

    int w = tid >> 5, lane = tid & 31;
    int c = lane * 2;

    for (int t = blockIdx.x; t < numTiles; t += gridDim.x) {
        int base = t * 16;
        for (int i = tid; i < 16 * F / 4; i += 256) {
            int node = base + i / (F / 4);
            ((float4*)shX)[i] = (node < n)
                ? ((const float4*)(x + (size_t)node * F))[i & (F / 4 - 1)]
                : make_float4(0.f, 0.f, 0.f, 0.f);
        }
        __syncthreads();

        float2 o0 = make_float2(0.f, 0.f), o1 = make_float2(0.f, 0.f);
        const float* a0p = shX + (2 * w) * F;
        const float* a1p = a0p + F;
        #pragma unroll 8
        for (int k = 0; k < F; k++) {
            float a0 = a0p[k], a1 = a1p[k];
            float2 wv = *(const float2*)(shW + k * 64 + c);
            o0.x += a0 * wv.x; o0.y += a0 * wv.y;
            o1.x += a1 * wv.x; o1.y += a1 * wv.y;
        }
        int m0 = base + 2 * w;
        if (m0 < n)     *(float2*)(y + (size_t)m0 * 64 + c) = o0;
        if (m0 + 1 < n) *(float2*)(y + (size_t)(m0 + 1) * 64 + c) = o1;
        __syncthreads();
    }
}

// ---------------- layer 3 aggregation (width 64) + bias + relu + head + sigmoid ----------------
__global__ void k_layer3(
    const float* __restrict__ y, const float* __restrict__ b3,
    const float* __restrict__ Wp, const float* __restrict__ bp,
    float* __restrict__ out, int n)
{
    int gw = (blockIdx.x * blockDim.x + threadIdx.x) >> 5;   // warp per node
    int lane = threadIdx.x & 31;
    if (gw >= n) return;
    int m = gw;
    int e = g_offsets[m], end = g_offsets[m + 1];
    float2 acc = make_float2(0.f, 0.f);
    const float* yb = y + (size_t)lane * 2;
    for (; e + 4 <= end; e += 4) {
        int i0 = g_csrsrc[e], i1 = g_csrsrc[e + 1];
        int i2 = g_csrsrc[e + 2], i3 = g_csrsrc[e + 3];
        float2 v0 = *(const float2*)(yb + (size_t)i0 * 64);
        float2 v1 = *(const float2*)(yb + (size_t)i1 * 64);
        float2 v2 = *(const float2*)(yb + (size_t)i2 * 64);
        float2 v3 = *(const float2*)(yb + (size_t)i3 * 64);
        acc.x += (v0.x + v1.x) + (v2.x + v3.x);
        acc.y += (v0.y + v1.y) + (v2.y + v3.y);
    }
    for (; e < end; e++) {
        int i0 = g_csrsrc[e];
        float2 v0 = *(const float2*)(yb + (size_t)i0 * 64);
        acc.x += v0.x; acc.y += v0.y;
    }
    float dn = g_dstnorm[m];
    float2 bb = *(const float2*)(b3 + lane * 2);
    float hx = fmaxf(acc.x * dn + bb.x, 0.f);
    float hy = fmaxf(acc.y * dn + bb.y, 0.f);
    float2 wp = *(const float2*)(Wp + lane * 2);
    float p = hx * wp.x + hy * wp.y;
    #pragma unroll
    for (int o = 16; o; o >>= 1) p += __shfl_xor_sync(0xffffffffu, p, o);
    if (lane == 0) {
        float l = p + bp[0];
        out[m] = 1.f / (1.f + __expf(-l));
    }
}

// ---------------- launch ----------------
extern "C" void kernel_launch(void* const* d_in, const int* in_sizes, int n_in,
                              void* d_out, int out_size)
{
    const float* feats = (const float*)d_in[0];
    const int*   src   = (const int*)d_in[1];
    const int*   dst   = (const int*)d_in[2];
    // d_in[3] = edge_types (unused)
    const float* W1 = (const float*)d_in[4];
    const float* b1 = (const float*)d_in[5];
    const float* W2 = (const float*)d_in[6];
    const float* b2 = (const float*)d_in[7];
    const float* W3 = (const float*)d_in[8];
    const float* b3 = (const float*)d_in[9];
    const float* Wp = (const float*)d_in[10];
    const float* bp = (const float*)d_in[11];
    float* out = (float*)d_out;

    int n = in_sizes[0] / F;   // 50000
    int e = in_sizes[1];       // 800000

    float *x0, *x1, *x2, *y;
    cudaGetSymbolAddress((void**)&x0, g_x0);
    cudaGetSymbolAddress((void**)&x1, g_x1);
    cudaGetSymbolAddress((void**)&x2, g_x2);
    cudaGetSymbolAddress((void**)&y,  g_y);

    size_t shl = (size_t)(F * F + 16 * F + F) * sizeof(float);   // 74240 B
    cudaFuncSetAttribute(k_layer128<true>,
                         cudaFuncAttributeMaxDynamicSharedMemorySize, (int)shl);

    int nb = (n + 1023) / 1024;
    int tiles = (n + 15) / 16;

    k_zero   <<<(n + 255) / 256, 256>>>(n);
    k_deg    <<<(e + 255) / 256, 256>>>(src, dst, e);
    k_norm   <<<(n + 255) / 256, 256>>>(n);
    k_scan1  <<<nb, 1024>>>(n);
    k_scan2  <<<1, 32>>>(nb);
    k_scan3  <<<(n + 255) / 256, 256>>>(n, e);
    k_scatter<<<(e + 255) / 256, 256>>>(src, dst, e);
    k_scale0 <<<(n * (F / 4) + 255) / 256, 256>>>(feats, n);

    k_layer128<true><<<444, 256, shl>>>(x0, W1, b1, x1, n, tiles);
    k_layer128<true><<<444, 256, shl>>>(x1, W2, b2, x2, n, tiles);
    k_pre3          <<<444, 256>>>(x2, W3, y, n, tiles);
    k_layer3        <<<(n * 32 + 255) / 256, 256>>>(y, b3, Wp, bp, out, n);
}

// round 2
// speedup vs baseline: 1.4243x; 1.4243x over previous
#include <cuda_runtime.h>
#include <math.h>

#define NN 50000
#define NE 800000
#define F  128

// ---------------- scratch (device globals; no allocation allowed) ----------------
__device__ int   g_outdeg[NN];
__device__ int   g_indeg[NN];
__device__ __align__(16) float g_srcnorm[NN];
__device__ __align__(16) float g_dstnorm[NN];
__device__ int   g_offsets[NN + 1];
__device__ int   g_cursor[NN];
__device__ int   g_csrsrc[NE];
__device__ int   g_blksums[64];
__device__ int   g_blkoffs[64];
__device__ __align__(16) float g_x0[(size_t)NN * F];
__device__ __align__(16) float g_x1[(size_t)NN * F];
__device__ __align__(16) float g_x2[(size_t)NN * F];
__device__ __align__(16) float g_y [(size_t)NN * 64];

// ---------------- tf32 mma helpers ----------------
__device__ __forceinline__ unsigned f2tf32(float x) {
    unsigned r;
    asm("cvt.rna.tf32.f32 %0, %1;" : "=r"(r) : "f"(x));
    return r;
}

__device__ __forceinline__ void mma_tf32(
    float& c0, float& c1, float& c2, float& c3,
    unsigned a0, unsigned a1, unsigned a2, unsigned a3,
    unsigned b0, unsigned b1)
{
    asm("mma.sync.aligned.m16n8k8.row.col.f32.tf32.tf32.f32 "
        "{%0,%1,%2,%3},{%4,%5,%6,%7},{%8,%9},{%0,%1,%2,%3};"
        : "+f"(c0), "+f"(c1), "+f"(c2), "+f"(c3)
        : "r"(a0), "r"(a1), "r"(a2), "r"(a3), "r"(b0), "r"(b1));
}

// ---------------- preprocessing: degrees, norms, CSR-by-dst ----------------
__global__ void k_zero(int n) {
    int i = blockIdx.x * blockDim.x + threadIdx.x;
    if (i < n) { g_outdeg[i] = 0; g_indeg[i] = 0; }
}

__global__ void k_deg(const int* __restrict__ src, const int* __restrict__ dst, int e) {
    int i = blockIdx.x * blockDim.x + threadIdx.x;
    if (i < e) {
        atomicAdd(&g_outdeg[src[i]], 1);
        atomicAdd(&g_indeg[dst[i]], 1);
    }
}

__global__ void k_norm(int n) {
    int i = blockIdx.x * blockDim.x + threadIdx.x;
    if (i < n) {
        int od = g_outdeg[i];
        int id = g_indeg[i];
        g_srcnorm[i] = od > 0 ? rsqrtf((float)od) : 0.f;
        g_dstnorm[i] = id > 0 ? rsqrtf((float)id) : 0.f;
    }
}

__global__ void k_scan1(int n) {
    __shared__ int sh[1024];
    int tid = threadIdx.x;
    int i = blockIdx.x * 1024 + tid;
    int v = (i < n) ? g_indeg[i] : 0;
    sh[tid] = v;
    __syncthreads();
    for (int off = 1; off < 1024; off <<= 1) {
        int t = (tid >= off) ? sh[tid - off] : 0;
        __syncthreads();
        sh[tid] += t;
        __syncthreads();
    }
    if (i < n) g_offsets[i] = sh[tid] - v;           // exclusive within block
    if (tid == 1023) g_blksums[blockIdx.x] = sh[1023];
}

__global__ void k_scan2(int nb) {
    if (blockIdx.x == 0 && threadIdx.x == 0) {
        int s = 0;
        for (int b = 0; b < nb; b++) { g_blkoffs[b] = s; s += g_blksums[b]; }
    }
}

__global__ void k_scan3(int n, int e) {
    int i = blockIdx.x * blockDim.x + threadIdx.x;
    if (i < n) {
        int o = g_offsets[i] + g_blkoffs[i >> 10];
        g_offsets[i] = o;
        g_cursor[i] = o;
    }
    if (i == 0) g_offsets[n] = e;
}

__global__ void k_scatter(const int* __restrict__ src, const int* __restrict__ dst, int e) {
    int i = blockIdx.x * blockDim.x + threadIdx.x;
    if (i < e) {
        int d = dst[i];
        int pos = atomicAdd(&g_cursor[d], 1);
        g_csrsrc[pos] = src[i];
    }
}

// x0 = features * src_norm[row]
__global__ void k_scale0(const float* __restrict__ feats, int n) {
    int i = blockIdx.x * blockDim.x + threadIdx.x;   // over n * (F/4) float4s
    if (i < n * (F / 4)) {
        int row = i / (F / 4);
        float4 v = ((const float4*)feats)[i];
        float s = g_srcnorm[row];
        v.x *= s; v.y *= s; v.z *= s; v.w *= s;
        ((float4*)g_x0)[i] = v;
    }
}

// ---------------- fused conv layer: gather-SpMM + tf32 MMA GEMM + relu (+ src_norm fold) ----
// persistent blocks, 256 threads (8 warps), tile = 16 nodes.
// smem: shWT = W transposed to [n][k], tf32-converted, padded stride 132 (conflict-free
//       B-fragment loads); shA = aggregated tile [16][132]; shB = bias.
#define PAD 132

template<bool FOLD_SRC_NORM>
__global__ void __launch_bounds__(256, 3) k_layer128(
    const float* __restrict__ xs, const float* __restrict__ W,
    const float* __restrict__ bias, float* __restrict__ out,
    int n, int numTiles)
{
    extern __shared__ float sh[];
    float* shWT = sh;                    // 128 * 132 floats (tf32 bits)
    float* shA  = sh + F * PAD;          // 16 * 132 floats
    float* shB  = shA + 16 * PAD;        // 128 floats

    int tid = threadIdx.x;
    // convert + transpose W: shWT[n][k] = tf32(W[k][n])
    unsigned* shWTu = (unsigned*)shWT;
    for (int i = tid; i < F * F; i += 256) {
        int k = i >> 7, nn = i & (F - 1);
        shWTu[nn * PAD + k] = f2tf32(W[i]);
    }
    if (tid < F / 4)
        ((float4*)shB)[tid] = ((const float4*)bias)[tid];
    __syncthreads();

    int w = tid >> 5, lane = tid & 31;
    int g = lane >> 2, tig = lane & 3;

    for (int t = blockIdx.x; t < numTiles; t += gridDim.x) {
        int base = t * 16;

        // --- aggregation: warp handles local nodes w and w+8 ---
        #pragma unroll
        for (int s2 = 0; s2 < 2; s2++) {
            int ml = w + s2 * 8;
            int m = base + ml;
            float4 acc = make_float4(0.f, 0.f, 0.f, 0.f);
            if (m < n) {
                int e = g_offsets[m], end = g_offsets[m + 1];
                const float* xb = xs + (size_t)lane * 4;
                for (; e + 4 <= end; e += 4) {
                    int i0 = g_csrsrc[e], i1 = g_csrsrc[e + 1];
                    int i2 = g_csrsrc[e + 2], i3 = g_csrsrc[e + 3];
                    float4 v0 = *(const float4*)(xb + (size_t)i0 * F);
                    float4 v1 = *(const float4*)(xb + (size_t)i1 * F);
                    float4 v2 = *(const float4*)(xb + (size_t)i2 * F);
                    float4 v3 = *(const float4*)(xb + (size_t)i3 * F);
                    acc.x += (v0.x + v1.x) + (v2.x + v3.x);
                    acc.y += (v0.y + v1.y) + (v2.y + v3.y);
                    acc.z += (v0.z + v1.z) + (v2.z + v3.z);
                    acc.w += (v0.w + v1.w) + (v2.w + v3.w);
                }
                for (; e < end; e++) {
                    int i0 = g_csrsrc[e];
                    float4 v0 = *(const float4*)(xb + (size_t)i0 * F);
                    acc.x += v0.x; acc.y += v0.y; acc.z += v0.z; acc.w += v0.w;
                }
                float dn = g_dstnorm[m];
                acc.x *= dn; acc.y *= dn; acc.z *= dn; acc.w *= dn;
            }
            float* p = shA + ml * PAD + lane * 4;
            *(float2*)p       = make_float2(acc.x, acc.y);
            *(float2*)(p + 2) = make_float2(acc.z, acc.w);
        }
        __syncthreads();

        // --- GEMM: warp w owns cols [16w, 16w+16) = two n-tiles of 8 ---
        int nb0 = w * 16, nb1 = nb0 + 8;
        float2 bb0 = *(float2*)(shB + nb0 + 2 * tig);
        float2 bb1 = *(float2*)(shB + nb1 + 2 * tig);
        float c00 = bb0.x, c01 = bb0.y, c02 = bb0.x, c03 = bb0.y;
        float c10 = bb1.x, c11 = bb1.y, c12 = bb1.x, c13 = bb1.y;

        #pragma unroll
        for (int kt = 0; kt < 16; kt++) {
            int kb = kt * 8;
            unsigned a0 = f2tf32(shA[g * PAD + kb + tig]);
            unsigned a1 = f2tf32(shA[(g + 8) * PAD + kb + tig]);
            unsigned a2 = f2tf32(shA[g * PAD + kb + tig + 4]);
            unsigned a3 = f2tf32(shA[(g + 8) * PAD + kb + tig + 4]);
            unsigned b00 = shWTu[(nb0 + g) * PAD + kb + tig];
            unsigned b01 = shWTu[(nb0 + g) * PAD + kb + tig + 4];
            unsigned b10 = shWTu[(nb1 + g) * PAD + kb + tig];
            unsigned b11 = shWTu[(nb1 + g) * PAD + kb + tig + 4];
            mma_tf32(c00, c01, c02, c03, a0, a1, a2, a3, b00, b01);
            mma_tf32(c10, c11, c12, c13, a0, a1, a2, a3, b10, b11);
        }

        // epilogue: relu (+ src_norm fold for next layer's gather operand)
        int m0 = base + g, m1 = base + g + 8;
        if (m0 < n) {
            float sn = FOLD_SRC_NORM ? g_srcnorm[m0] : 1.f;
            *(float2*)(out + (size_t)m0 * F + nb0 + 2 * tig) =
                make_float2(fmaxf(c00, 0.f) * sn, fmaxf(c01, 0.f) * sn);
            *(float2*)(out + (size_t)m0 * F + nb1 + 2 * tig) =
                make_float2(fmaxf(c10, 0.f) * sn, fmaxf(c11, 0.f) * sn);
        }
        if (m1 < n) {
            float sn = FOLD_SRC_NORM ? g_srcnorm[m1] : 1.f;
            *(float2*)(out + (size_t)m1 * F + nb0 + 2 * tig) =
                make_float2(fmaxf(c02, 0.f) * sn, fmaxf(c03, 0.f) * sn);
            *(float2*)(out + (size_t)m1 * F + nb1 + 2 * tig) =
                make_float2(fmaxf(c12, 0.f) * sn, fmaxf(c13, 0.f) * sn);
        }
        __syncthreads();
    }
}

// ---------------- y = x2s @ W3 via tf32 MMA (project BEFORE last SpMM) ----------------
__global__ void __launch_bounds__(256) k_pre3(
    const float* __restrict__ x, const float* __restrict__ W3,
    float* __restrict__ y, int n, int numTiles)
{
    __shared__ float shWT[64 * PAD];   // tf32 bits, [n][k]
    __shared__ float shX[16 * PAD];
    int tid = threadIdx.x;
    unsigned* shWTu = (unsigned*)shWT;
    for (int i = tid; i < F * 64; i += 256) {
        int k = i >> 6, nn = i & 63;
        shWTu[nn * PAD + k] = f2tf32(W3[i]);
    }
    __syncthreads();

    int w = tid >> 5, lane = tid & 31;
    int g = lane >> 2, tig = lane & 3;

    for (int t = blockIdx.x; t < numTiles; t += gridDim.x) {
        int base = t * 16;
        // load X tile (padded)
        for (int i = tid; i < 16 * (F / 4); i += 256) {
            int r = i >> 5;
            int cc = (i & 31) * 4;
            int node = base + r;
            float4 v = (node < n)
                ? ((const float4*)(x + (size_t)node * F))[i & 31]
                : make_float4(0.f, 0.f, 0.f, 0.f);
            float* p = shX + r * PAD + cc;
            *(float2*)p       = make_float2(v.x, v.y);
            *(float2*)(p + 2) = make_float2(v.z, v.w);
        }
        __syncthreads();

        int nb = w * 8;   // warp owns 8 cols
        float c0 = 0.f, c1 = 0.f, c2 = 0.f, c3 = 0.f;
        #pragma unroll
        for (int kt = 0; kt < 16; kt++) {
            int kb = kt * 8;
            unsigned a0 = f2tf32(shX[g * PAD + kb + tig]);
            unsigned a1 = f2tf32(shX[(g + 8) * PAD + kb + tig]);
            unsigned a2 = f2tf32(shX[g * PAD + kb + tig + 4]);
            unsigned a3 = f2tf32(shX[(g + 8) * PAD + kb + tig + 4]);
            unsigned b0 = shWTu[(nb + g) * PAD + kb + tig];
            unsigned b1 = shWTu[(nb + g) * PAD + kb + tig + 4];
            mma_tf32(c0, c1, c2, c3, a0, a1, a2, a3, b0, b1);
        }

        int m0 = base + g, m1 = base + g + 8;
        if (m0 < n) *(float2*)(y + (size_t)m0 * 64 + nb + 2 * tig) = make_float2(c0, c1);
        if (m1 < n) *(float2*)(y + (size_t)m1 * 64 + nb + 2 * tig) = make_float2(c2, c3);
        __syncthreads();
    }
}

// ---------------- layer 3 aggregation (width 64) + bias + relu + head + sigmoid ----------------
__global__ void k_layer3(
    const float* __restrict__ y, const float* __restrict__ b3,
    const float* __restrict__ Wp, const float* __restrict__ bp,
    float* __restrict__ out, int n)
{
    int gw = (blockIdx.x * blockDim.x + threadIdx.x) >> 5;   // warp per node
    int lane = threadIdx.x & 31;
    if (gw >= n) return;
    int m = gw;
    int e = g_offsets[m], end = g_offsets[m + 1];
    float2 acc = make_float2(0.f, 0.f);
    const float* yb = y + (size_t)lane * 2;
    for (; e + 4 <= end; e += 4) {
        int i0 = g_csrsrc[e], i1 = g_csrsrc[e + 1];
        int i2 = g_csrsrc[e + 2], i3 = g_csrsrc[e + 3];
        float2 v0 = *(const float2*)(yb + (size_t)i0 * 64);
        float2 v1 = *(const float2*)(yb + (size_t)i1 * 64);
        float2 v2 = *(const float2*)(yb + (size_t)i2 * 64);
        float2 v3 = *(const float2*)(yb + (size_t)i3 * 64);
        acc.x += (v0.x + v1.x) + (v2.x + v3.x);
        acc.y += (v0.y + v1.y) + (v2.y + v3.y);
    }
    for (; e < end; e++) {
        int i0 = g_csrsrc[e];
        float2 v0 = *(const float2*)(yb + (size_t)i0 * 64);
        acc.x += v0.x; acc.y += v0.y;
    }
    float dn = g_dstnorm[m];
    float2 bb = *(const float2*)(b3 + lane * 2);
    float hx = fmaxf(acc.x * dn + bb.x, 0.f);
    float hy = fmaxf(acc.y * dn + bb.y, 0.f);
    float2 wp = *(const float2*)(Wp + lane * 2);
    float p = hx * wp.x + hy * wp.y;
    #pragma unroll
    for (int o = 16; o; o >>= 1) p += __shfl_xor_sync(0xffffffffu, p, o);
    if (lane == 0) {
        float l = p + bp[0];
        out[m] = 1.f / (1.f + __expf(-l));
    }
}

// ---------------- launch ----------------
extern "C" void kernel_launch(void* const* d_in, const int* in_sizes, int n_in,
                              void* d_out, int out_size)
{
    const float* feats = (const float*)d_in[0];
    const int*   src   = (const int*)d_in[1];
    const int*   dst   = (const int*)d_in[2];
    // d_in[3] = edge_types (unused)
    const float* W1 = (const float*)d_in[4];
    const float* b1 = (const float*)d_in[5];
    const float* W2 = (const float*)d_in[6];
    const float* b2 = (const float*)d_in[7];
    const float* W3 = (const float*)d_in[8];
    const float* b3 = (const float*)d_in[9];
    const float* Wp = (const float*)d_in[10];
    const float* bp = (const float*)d_in[11];
    float* out = (float*)d_out;

    int n = in_sizes[0] / F;   // 50000
    int e = in_sizes[1];       // 800000

    float *x0, *x1, *x2, *y;
    cudaGetSymbolAddress((void**)&x0, g_x0);
    cudaGetSymbolAddress((void**)&x1, g_x1);
    cudaGetSymbolAddress((void**)&x2, g_x2);
    cudaGetSymbolAddress((void**)&y,  g_y);

    size_t shl = (size_t)(F * PAD + 16 * PAD + F) * sizeof(float);   // ~76.5 KB
    cudaFuncSetAttribute(k_layer128<true>,
                         cudaFuncAttributeMaxDynamicSharedMemorySize, (int)shl);

    int nb = (n + 1023) / 1024;
    int tiles = (n + 15) / 16;

    k_zero   <<<(n + 255) / 256, 256>>>(n);
    k_deg    <<<(e + 255) / 256, 256>>>(src, dst, e);
    k_norm   <<<(n + 255) / 256, 256>>>(n);
    k_scan1  <<<nb, 1024>>>(n);
    k_scan2  <<<1, 32>>>(nb);
    k_scan3  <<<(n + 255) / 256, 256>>>(n, e);
    k_scatter<<<(e + 255) / 256, 256>>>(src, dst, e);
    k_scale0 <<<(n * (F / 4) + 255) / 256, 256>>>(feats, n);

    k_layer128<true><<<444, 256, shl>>>(x0, W1, b1, x1, n, tiles);
    k_layer128<true><<<444, 256, shl>>>(x1, W2, b2, x2, n, tiles);
    k_pre3          <<<444, 256>>>(x2, W3, y, n, tiles);
    k_layer3        <<<(n * 32 + 255) / 256, 256>>>(y, b3, Wp, bp, out, n);
}

// round 3
// speedup vs baseline: 1.4458x; 1.0151x over previous
#include <cuda_runtime.h>
#include <math.h>

#define NN 50000
#define NE 800000
#define F  128

// ---------------- scratch (device globals; no allocation allowed) ----------------
__device__ int   g_outdeg[NN];
__device__ int   g_indeg[NN];
__device__ __align__(16) float g_srcnorm[NN];
__device__ __align__(16) float g_dstnorm[NN];
__device__ int   g_offsets[NN + 1];
__device__ int   g_cursor[NN];
__device__ int   g_csrsrc[NE];
__device__ int   g_blksums[64];
__device__ int   g_blkoffs[64];
// bf16-packed gather operands (2 values per unsigned)
__device__ __align__(16) unsigned g_h0[(size_t)NN * F / 2];
__device__ __align__(16) unsigned g_h1[(size_t)NN * F / 2];
__device__ __align__(16) unsigned g_hy[(size_t)NN * 64 / 2];
__device__ __align__(16) float    g_x2[(size_t)NN * F];

// ---------------- helpers ----------------
__device__ __forceinline__ unsigned f2tf32(float x) {
    unsigned r;
    asm("cvt.rna.tf32.f32 %0, %1;" : "=r"(r) : "f"(x));
    return r;
}

// pack (lo, hi) floats into bf16x2 (hi in upper 16 bits)
__device__ __forceinline__ unsigned pack_bf2(float lo, float hi) {
    unsigned r;
    asm("cvt.rn.bf16x2.f32 %0, %1, %2;" : "=r"(r) : "f"(hi), "f"(lo));
    return r;
}
// unpack without cvt: pure ALU
#define BF_LO(u) __uint_as_float((u) << 16)
#define BF_HI(u) __uint_as_float((u) & 0xffff0000u)

__device__ __forceinline__ void mma_tf32(
    float& c0, float& c1, float& c2, float& c3,
    unsigned a0, unsigned a1, unsigned a2, unsigned a3,
    unsigned b0, unsigned b1)
{
    asm("mma.sync.aligned.m16n8k8.row.col.f32.tf32.tf32.f32 "
        "{%0,%1,%2,%3},{%4,%5,%6,%7},{%8,%9},{%0,%1,%2,%3};"
        : "+f"(c0), "+f"(c1), "+f"(c2), "+f"(c3)
        : "r"(a0), "r"(a1), "r"(a2), "r"(a3), "r"(b0), "r"(b1));
}

// ---------------- preprocessing: degrees, norms, CSR-by-dst ----------------
__global__ void k_zero(int n) {
    int i = blockIdx.x * blockDim.x + threadIdx.x;
    if (i < n) { g_outdeg[i] = 0; g_indeg[i] = 0; }
}

__global__ void k_deg(const int* __restrict__ src, const int* __restrict__ dst, int e) {
    int i = blockIdx.x * blockDim.x + threadIdx.x;
    if (i < e) {
        atomicAdd(&g_outdeg[src[i]], 1);
        atomicAdd(&g_indeg[dst[i]], 1);
    }
}

__global__ void k_norm(int n) {
    int i = blockIdx.x * blockDim.x + threadIdx.x;
    if (i < n) {
        int od = g_outdeg[i];
        int id = g_indeg[i];
        g_srcnorm[i] = od > 0 ? rsqrtf((float)od) : 0.f;
        g_dstnorm[i] = id > 0 ? rsqrtf((float)id) : 0.f;
    }
}

__global__ void k_scan1(int n) {
    __shared__ int sh[1024];
    int tid = threadIdx.x;
    int i = blockIdx.x * 1024 + tid;
    int v = (i < n) ? g_indeg[i] : 0;
    sh[tid] = v;
    __syncthreads();
    for (int off = 1; off < 1024; off <<= 1) {
        int t = (tid >= off) ? sh[tid - off] : 0;
        __syncthreads();
        sh[tid] += t;
        __syncthreads();
    }
    if (i < n) g_offsets[i] = sh[tid] - v;
    if (tid == 1023) g_blksums[blockIdx.x] = sh[1023];
}

__global__ void k_scan2(int nb) {
    if (blockIdx.x == 0 && threadIdx.x == 0) {
        int s = 0;
        for (int b = 0; b < nb; b++) { g_blkoffs[b] = s; s += g_blksums[b]; }
    }
}

__global__ void k_scan3(int n, int e) {
    int i = blockIdx.x * blockDim.x + threadIdx.x;
    if (i < n) {
        int o = g_offsets[i] + g_blkoffs[i >> 10];
        g_offsets[i] = o;
        g_cursor[i] = o;
    }
    if (i == 0) g_offsets[n] = e;
}

__global__ void k_scatter(const int* __restrict__ src, const int* __restrict__ dst, int e) {
    int i = blockIdx.x * blockDim.x + threadIdx.x;
    if (i < e) {
        int d = dst[i];
        int pos = atomicAdd(&g_cursor[d], 1);
        g_csrsrc[pos] = src[i];
    }
}

// h0 = bf16(features * src_norm[row]) ; one thread per 4 floats
__global__ void k_scale0(const float* __restrict__ feats, int n) {
    int i = blockIdx.x * blockDim.x + threadIdx.x;   // over n * (F/4)
    if (i < n * (F / 4)) {
        int row = i / (F / 4);
        float4 v = ((const float4*)feats)[i];
        float s = g_srcnorm[row];
        uint2 o;
        o.x = pack_bf2(v.x * s, v.y * s);
        o.y = pack_bf2(v.z * s, v.w * s);
        ((uint2*)g_h0)[i] = o;
    }
}

// ---------------- fused conv layer: bf16 gather-SpMM + tf32 MMA GEMM + relu + src_norm fold ----
#define PAD 132

template<bool HALF_OUT>
__global__ void __launch_bounds__(256, 3) k_layer128(
    const unsigned* __restrict__ xs,      // bf16-packed, row stride F/2 uints
    const float* __restrict__ W,
    const float* __restrict__ bias, void* __restrict__ outv,
    int n, int numTiles)
{
    extern __shared__ float sh[];
    float* shWT = sh;                    // 128 * 132 (tf32 bits)
    float* shA  = sh + F * PAD;          // 16 * 132
    float* shB  = shA + 16 * PAD;        // 128

    int tid = threadIdx.x;
    unsigned* shWTu = (unsigned*)shWT;
    for (int i = tid; i < F * F; i += 256) {
        int k = i >> 7, nn = i & (F - 1);
        shWTu[nn * PAD + k] = f2tf32(W[i]);
    }
    if (tid < F / 4)
        ((float4*)shB)[tid] = ((const float4*)bias)[tid];
    __syncthreads();

    int w = tid >> 5, lane = tid & 31;
    int g = lane >> 2, tig = lane & 3;

    for (int t = blockIdx.x; t < numTiles; t += gridDim.x) {
        int base = t * 16;

        // --- aggregation: warp handles local nodes w and w+8; lane covers 4 cols ---
        #pragma unroll
        for (int s2 = 0; s2 < 2; s2++) {
            int ml = w + s2 * 8;
            int m = base + ml;
            float4 acc = make_float4(0.f, 0.f, 0.f, 0.f);
            if (m < n) {
                int e = g_offsets[m], end = g_offsets[m + 1];
                const unsigned* xb = xs + lane * 2;   // 2 uints = 4 bf16 vals
                for (; e + 4 <= end; e += 4) {
                    int i0 = g_csrsrc[e], i1 = g_csrsrc[e + 1];
                    int i2 = g_csrsrc[e + 2], i3 = g_csrsrc[e + 3];
                    uint2 u0 = *(const uint2*)(xb + (size_t)i0 * (F / 2));
                    uint2 u1 = *(const uint2*)(xb + (size_t)i1 * (F / 2));
                    uint2 u2 = *(const uint2*)(xb + (size_t)i2 * (F / 2));
                    uint2 u3 = *(const uint2*)(xb + (size_t)i3 * (F / 2));
                    acc.x += (BF_LO(u0.x) + BF_LO(u1.x)) + (BF_LO(u2.x) + BF_LO(u3.x));
                    acc.y += (BF_HI(u0.x) + BF_HI(u1.x)) + (BF_HI(u2.x) + BF_HI(u3.x));
                    acc.z += (BF_LO(u0.y) + BF_LO(u1.y)) + (BF_LO(u2.y) + BF_LO(u3.y));
                    acc.w += (BF_HI(u0.y) + BF_HI(u1.y)) + (BF_HI(u2.y) + BF_HI(u3.y));
                }
                for (; e < end; e++) {
                    int i0 = g_csrsrc[e];
                    uint2 u0 = *(const uint2*)(xb + (size_t)i0 * (F / 2));
                    acc.x += BF_LO(u0.x); acc.y += BF_HI(u0.x);
                    acc.z += BF_LO(u0.y); acc.w += BF_HI(u0.y);
                }
                float dn = g_dstnorm[m];
                acc.x *= dn; acc.y *= dn; acc.z *= dn; acc.w *= dn;
            }
            float* p = shA + ml * PAD + lane * 4;
            *(float2*)p       = make_float2(acc.x, acc.y);
            *(float2*)(p + 2) = make_float2(acc.z, acc.w);
        }
        __syncthreads();

        // --- GEMM: warp w owns cols [16w, 16w+16) ---
        int nb0 = w * 16, nb1 = nb0 + 8;
        float2 bb0 = *(float2*)(shB + nb0 + 2 * tig);
        float2 bb1 = *(float2*)(shB + nb1 + 2 * tig);
        float c00 = bb0.x, c01 = bb0.y, c02 = bb0.x, c03 = bb0.y;
        float c10 = bb1.x, c11 = bb1.y, c12 = bb1.x, c13 = bb1.y;

        #pragma unroll
        for (int kt = 0; kt < 16; kt++) {
            int kb = kt * 8;
            unsigned a0 = f2tf32(shA[g * PAD + kb + tig]);
            unsigned a1 = f2tf32(shA[(g + 8) * PAD + kb + tig]);
            unsigned a2 = f2tf32(shA[g * PAD + kb + tig + 4]);
            unsigned a3 = f2tf32(shA[(g + 8) * PAD + kb + tig + 4]);
            unsigned b00 = shWTu[(nb0 + g) * PAD + kb + tig];
            unsigned b01 = shWTu[(nb0 + g) * PAD + kb + tig + 4];
            unsigned b10 = shWTu[(nb1 + g) * PAD + kb + tig];
            unsigned b11 = shWTu[(nb1 + g) * PAD + kb + tig + 4];
            mma_tf32(c00, c01, c02, c03, a0, a1, a2, a3, b00, b01);
            mma_tf32(c10, c11, c12, c13, a0, a1, a2, a3, b10, b11);
        }

        // epilogue: relu + src_norm fold; bf16 or fp32 out
        int m0 = base + g, m1 = base + g + 8;
        if (m0 < n) {
            float sn = g_srcnorm[m0];
            float v0 = fmaxf(c00, 0.f) * sn, v1 = fmaxf(c01, 0.f) * sn;
            float v2 = fmaxf(c10, 0.f) * sn, v3 = fmaxf(c11, 0.f) * sn;
            if (HALF_OUT) {
                unsigned* o = (unsigned*)outv + (size_t)m0 * (F / 2);
                o[nb0 / 2 + tig] = pack_bf2(v0, v1);
                o[nb1 / 2 + tig] = pack_bf2(v2, v3);
            } else {
                float* o = (float*)outv + (size_t)m0 * F;
                *(float2*)(o + nb0 + 2 * tig) = make_float2(v0, v1);
                *(float2*)(o + nb1 + 2 * tig) = make_float2(v2, v3);
            }
        }
        if (m1 < n) {
            float sn = g_srcnorm[m1];
            float v0 = fmaxf(c02, 0.f) * sn, v1 = fmaxf(c03, 0.f) * sn;
            float v2 = fmaxf(c12, 0.f) * sn, v3 = fmaxf(c13, 0.f) * sn;
            if (HALF_OUT) {
                unsigned* o = (unsigned*)outv + (size_t)m1 * (F / 2);
                o[nb0 / 2 + tig] = pack_bf2(v0, v1);
                o[nb1 / 2 + tig] = pack_bf2(v2, v3);
            } else {
                float* o = (float*)outv + (size_t)m1 * F;
                *(float2*)(o + nb0 + 2 * tig) = make_float2(v0, v1);
                *(float2*)(o + nb1 + 2 * tig) = make_float2(v2, v3);
            }
        }
        __syncthreads();
    }
}

// ---------------- y = x2s @ W3 via tf32 MMA, bf16 output (project BEFORE last SpMM) --------
__global__ void __launch_bounds__(256) k_pre3(
    const float* __restrict__ x, const float* __restrict__ W3,
    unsigned* __restrict__ y, int n, int numTiles)
{
    __shared__ float shWT[64 * PAD];
    __shared__ float shX[16 * PAD];
    int tid = threadIdx.x;
    unsigned* shWTu = (unsigned*)shWT;
    for (int i = tid; i < F * 64; i += 256) {
        int k = i >> 6, nn = i & 63;
        shWTu[nn * PAD + k] = f2tf32(W3[i]);
    }
    __syncthreads();

    int w = tid >> 5, lane = tid & 31;
    int g = lane >> 2, tig = lane & 3;

    for (int t = blockIdx.x; t < numTiles; t += gridDim.x) {
        int base = t * 16;
        for (int i = tid; i < 16 * (F / 4); i += 256) {
            int r = i >> 5;
            int cc = (i & 31) * 4;
            int node = base + r;
            float4 v = (node < n)
                ? ((const float4*)(x + (size_t)node * F))[i & 31]
                : make_float4(0.f, 0.f, 0.f, 0.f);
            float* p = shX + r * PAD + cc;
            *(float2*)p       = make_float2(v.x, v.y);
            *(float2*)(p + 2) = make_float2(v.z, v.w);
        }
        __syncthreads();

        int nb = w * 8;
        float c0 = 0.f, c1 = 0.f, c2 = 0.f, c3 = 0.f;
        #pragma unroll
        for (int kt = 0; kt < 16; kt++) {
            int kb = kt * 8;
            unsigned a0 = f2tf32(shX[g * PAD + kb + tig]);
            unsigned a1 = f2tf32(shX[(g + 8) * PAD + kb + tig]);
            unsigned a2 = f2tf32(shX[g * PAD + kb + tig + 4]);
            unsigned a3 = f2tf32(shX[(g + 8) * PAD + kb + tig + 4]);
            unsigned b0 = shWTu[(nb + g) * PAD + kb + tig];
            unsigned b1 = shWTu[(nb + g) * PAD + kb + tig + 4];
            mma_tf32(c0, c1, c2, c3, a0, a1, a2, a3, b0, b1);
        }

        int m0 = base + g, m1 = base + g + 8;
        if (m0 < n) y[(size_t)m0 * 32 + nb / 2 + tig] = pack_bf2(c0, c1);
        if (m1 < n) y[(size_t)m1 * 32 + nb / 2 + tig] = pack_bf2(c2, c3);
        __syncthreads();
    }
}

// ---------------- layer 3 aggregation (bf16, width 64) + bias + relu + head + sigmoid ------
__global__ void k_layer3(
    const unsigned* __restrict__ y, const float* __restrict__ b3,
    const float* __restrict__ Wp, const float* __restrict__ bp,
    float* __restrict__ out, int n)
{
    int gw = (blockIdx.x * blockDim.x + threadIdx.x) >> 5;   // warp per node
    int lane = threadIdx.x & 31;
    if (gw >= n) return;
    int m = gw;
    int e = g_offsets[m], end = g_offsets[m + 1];
    float2 acc = make_float2(0.f, 0.f);
    const unsigned* yb = y + lane;   // 1 uint = 2 bf16 vals; row stride 32
    for (; e + 4 <= end; e += 4) {
        int i0 = g_csrsrc[e], i1 = g_csrsrc[e + 1];
        int i2 = g_csrsrc[e + 2], i3 = g_csrsrc[e + 3];
        unsigned u0 = yb[(size_t)i0 * 32];
        unsigned u1 = yb[(size_t)i1 * 32];
        unsigned u2 = yb[(size_t)i2 * 32];
        unsigned u3 = yb[(size_t)i3 * 32];
        acc.x += (BF_LO(u0) + BF_LO(u1)) + (BF_LO(u2) + BF_LO(u3));
        acc.y += (BF_HI(u0) + BF_HI(u1)) + (BF_HI(u2) + BF_HI(u3));
    }
    for (; e < end; e++) {
        unsigned u0 = yb[(size_t)g_csrsrc[e] * 32];
        acc.x += BF_LO(u0); acc.y += BF_HI(u0);
    }
    float dn = g_dstnorm[m];
    float2 bb = *(const float2*)(b3 + lane * 2);
    float hx = fmaxf(acc.x * dn + bb.x, 0.f);
    float hy = fmaxf(acc.y * dn + bb.y, 0.f);
    float2 wp = *(const float2*)(Wp + lane * 2);
    float p = hx * wp.x + hy * wp.y;
    #pragma unroll
    for (int o = 16; o; o >>= 1) p += __shfl_xor_sync(0xffffffffu, p, o);
    if (lane == 0) {
        float l = p + bp[0];
        out[m] = 1.f / (1.f + __expf(-l));
    }
}

// ---------------- launch ----------------
extern "C" void kernel_launch(void* const* d_in, const int* in_sizes, int n_in,
                              void* d_out, int out_size)
{
    const float* feats = (const float*)d_in[0];
    const int*   src   = (const int*)d_in[1];
    const int*   dst   = (const int*)d_in[2];
    // d_in[3] = edge_types (unused)
    const float* W1 = (const float*)d_in[4];
    const float* b1 = (const float*)d_in[5];
    const float* W2 = (const float*)d_in[6];
    const float* b2 = (const float*)d_in[7];
    const float* W3 = (const float*)d_in[8];
    const float* b3 = (const float*)d_in[9];
    const float* Wp = (const float*)d_in[10];
    const float* bp = (const float*)d_in[11];
    float* out = (float*)d_out;

    int n = in_sizes[0] / F;   // 50000
    int e = in_sizes[1];       // 800000

    unsigned *h0, *h1, *hy;
    float *x2;
    cudaGetSymbolAddress((void**)&h0, g_h0);
    cudaGetSymbolAddress((void**)&h1, g_h1);
    cudaGetSymbolAddress((void**)&hy, g_hy);
    cudaGetSymbolAddress((void**)&x2, g_x2);

    size_t shl = (size_t)(F * PAD + 16 * PAD + F) * sizeof(float);
    cudaFuncSetAttribute(k_layer128<true>,
                         cudaFuncAttributeMaxDynamicSharedMemorySize, (int)shl);
    cudaFuncSetAttribute(k_layer128<false>,
                         cudaFuncAttributeMaxDynamicSharedMemorySize, (int)shl);

    int nb = (n + 1023) / 1024;
    int tiles = (n + 15) / 16;

    k_zero   <<<(n + 255) / 256, 256>>>(n);
    k_deg    <<<(e + 255) / 256, 256>>>(src, dst, e);
    k_norm   <<<(n + 255) / 256, 256>>>(n);
    k_scan1  <<<nb, 1024>>>(n);
    k_scan2  <<<1, 32>>>(nb);
    k_scan3  <<<(n + 255) / 256, 256>>>(n, e);
    k_scatter<<<(e + 255) / 256, 256>>>(src, dst, e);
    k_scale0 <<<(n * (F / 4) + 255) / 256, 256>>>(feats, n);

    k_layer128<true> <<<444, 256, shl>>>(h0, W1, b1, h1, n, tiles);
    k_layer128<false><<<444, 256, shl>>>(h1, W2, b2, x2, n, tiles);
    k_pre3           <<<444, 256>>>(x2, W3, hy, n, tiles);
    k_layer3         <<<(n * 32 + 255) / 256, 256>>>(hy, b3, Wp, bp, out, n);
}

// round 4
// speedup vs baseline: 2.0315x; 1.4051x over previous
#include <cuda_runtime.h>
#include <math.h>

#define NN 50000
#define NE 800000
#define F  128
#define AP 68   // padded row stride (uints) for bf16x2 smem tiles: banks 4g+tig, conflict-free

// ---------------- scratch (device globals; no allocation allowed) ----------------
__device__ int   g_outdeg[NN];
__device__ int   g_indeg[NN];
__device__ __align__(16) float g_srcnorm[NN];
__device__ __align__(16) float g_dstnorm[NN];
__device__ int   g_offsets[NN + 1];
__device__ int   g_cursor[NN];
__device__ int   g_csrsrc[NE];
__device__ int   g_blksums[64];
__device__ int   g_blkoffs[64];
// bf16-packed feature buffers (2 vals per uint)
__device__ __align__(16) unsigned g_h0[(size_t)NN * F / 2];
__device__ __align__(16) unsigned g_h1[(size_t)NN * F / 2];
__device__ __align__(16) unsigned g_hy[(size_t)NN * 64 / 2];

// ---------------- helpers ----------------
// pack (lo, hi) floats into bf16x2 (hi in upper 16 bits)
__device__ __forceinline__ unsigned pack_bf2(float lo, float hi) {
    unsigned r;
    asm("cvt.rn.bf16x2.f32 %0, %1, %2;" : "=r"(r) : "f"(hi), "f"(lo));
    return r;
}
// unpack without cvt: pure ALU
#define BF_LO(u) __uint_as_float((u) << 16)
#define BF_HI(u) __uint_as_float((u) & 0xffff0000u)

__device__ __forceinline__ void mma_bf16(
    float& c0, float& c1, float& c2, float& c3,
    unsigned a0, unsigned a1, unsigned a2, unsigned a3,
    unsigned b0, unsigned b1)
{
    asm("mma.sync.aligned.m16n8k16.row.col.f32.bf16.bf16.f32 "
        "{%0,%1,%2,%3},{%4,%5,%6,%7},{%8,%9},{%0,%1,%2,%3};"
        : "+f"(c0), "+f"(c1), "+f"(c2), "+f"(c3)
        : "r"(a0), "r"(a1), "r"(a2), "r"(a3), "r"(b0), "r"(b1));
}

// ---------------- preprocessing: degrees, norms, CSR-by-dst ----------------
__global__ void k_zero(int n) {
    int i = blockIdx.x * blockDim.x + threadIdx.x;
    if (i < n) { g_outdeg[i] = 0; g_indeg[i] = 0; }
}

__global__ void k_deg(const int* __restrict__ src, const int* __restrict__ dst, int e) {
    int i = blockIdx.x * blockDim.x + threadIdx.x;
    if (i < e) {
        atomicAdd(&g_outdeg[src[i]], 1);
        atomicAdd(&g_indeg[dst[i]], 1);
    }
}

__global__ void k_scan1(int n) {
    __shared__ int sh[1024];
    int tid = threadIdx.x;
    int i = blockIdx.x * 1024 + tid;
    int v = (i < n) ? g_indeg[i] : 0;
    sh[tid] = v;
    __syncthreads();
    for (int off = 1; off < 1024; off <<= 1) {
        int t = (tid >= off) ? sh[tid - off] : 0;
        __syncthreads();
        sh[tid] += t;
        __syncthreads();
    }
    if (i < n) g_offsets[i] = sh[tid] - v;
    if (tid == 1023) g_blksums[blockIdx.x] = sh[1023];
}

__global__ void k_scan2(int nb) {
    if (blockIdx.x == 0 && threadIdx.x == 0) {
        int s = 0;
        for (int b = 0; b < nb; b++) { g_blkoffs[b] = s; s += g_blksums[b]; }
    }
}

// finish scan + compute norms (fused)
__global__ void k_scan3(int n, int e) {
    int i = blockIdx.x * blockDim.x + threadIdx.x;
    if (i < n) {
        int o = g_offsets[i] + g_blkoffs[i >> 10];
        g_offsets[i] = o;
        g_cursor[i] = o;
        int od = g_outdeg[i];
        int id = g_indeg[i];
        g_srcnorm[i] = od > 0 ? rsqrtf((float)od) : 0.f;
        g_dstnorm[i] = id > 0 ? rsqrtf((float)id) : 0.f;
    }
    if (i == 0) g_offsets[n] = e;
}

__global__ void k_scatter(const int* __restrict__ src, const int* __restrict__ dst, int e) {
    int i = blockIdx.x * blockDim.x + threadIdx.x;
    if (i < e) {
        int d = dst[i];
        int pos = atomicAdd(&g_cursor[d], 1);
        g_csrsrc[pos] = src[i];
    }
}

// h0 = bf16(features * src_norm[row])
__global__ void k_scale0(const float* __restrict__ feats, int n) {
    int i = blockIdx.x * blockDim.x + threadIdx.x;   // over n * (F/4)
    if (i < n * (F / 4)) {
        int row = i / (F / 4);
        float4 v = ((const float4*)feats)[i];
        float s = g_srcnorm[row];
        uint2 o;
        o.x = pack_bf2(v.x * s, v.y * s);
        o.y = pack_bf2(v.z * s, v.w * s);
        ((uint2*)g_h0)[i] = o;
    }
}

// ---------------- fused conv layer: bf16 gather-SpMM + bf16 MMA GEMM + relu + src_norm fold ----
// 256 threads, tile = 16 nodes. smem ~39.7 KB -> 5 blocks/SM (40 warps/SM).
__global__ void __launch_bounds__(256, 5) k_layer128(
    const unsigned* __restrict__ xs,      // bf16-packed, row stride F/2 uints
    const float* __restrict__ W,          // [F][F] row-major fp32
    const float* __restrict__ bias,
    unsigned* __restrict__ out,           // bf16-packed output
    int n, int numTiles)
{
    __shared__ unsigned shWb[F * AP];     // [n][k/2] bf16x2  (34816 B)
    __shared__ unsigned shAb[16 * AP];    // aggregated tile, bf16x2 (4352 B)
    __shared__ float    shB[F];           // bias (512 B)

    int tid = threadIdx.x;
    // convert W -> bf16x2, transposed to [n][k/2]; coalesced LDG (lanes sweep n)
    for (int i = tid; i < F * (F / 2); i += 256) {
        int k2 = i >> 7, nn = i & (F - 1);
        shWb[nn * AP + k2] = pack_bf2(W[(2 * k2) * F + nn], W[(2 * k2 + 1) * F + nn]);
    }
    if (tid < F / 4) ((float4*)shB)[tid] = ((const float4*)bias)[tid];
    __syncthreads();

    int w = tid >> 5, lane = tid & 31;
    int g = lane >> 2, tig = lane & 3;

    for (int t = blockIdx.x; t < numTiles; t += gridDim.x) {
        int base = t * 16;

        // --- aggregation: warp handles local nodes w and w+8; lane covers 4 k-cols ---
        #pragma unroll
        for (int s2 = 0; s2 < 2; s2++) {
            int ml = w + s2 * 8;
            int m = base + ml;
            float4 acc = make_float4(0.f, 0.f, 0.f, 0.f);
            if (m < n) {
                int e = g_offsets[m], end = g_offsets[m + 1];
                const unsigned* xb = xs + lane * 2;
                for (; e + 8 <= end; e += 8) {
                    uint2 u[8];
                    #pragma unroll
                    for (int q = 0; q < 8; q++) {
                        int idx = g_csrsrc[e + q];
                        u[q] = *(const uint2*)(xb + (size_t)idx * (F / 2));
                    }
                    #pragma unroll
                    for (int q = 0; q < 8; q++) {
                        acc.x += BF_LO(u[q].x); acc.y += BF_HI(u[q].x);
                        acc.z += BF_LO(u[q].y); acc.w += BF_HI(u[q].y);
                    }
                }
                for (; e + 4 <= end; e += 4) {
                    uint2 u[4];
                    #pragma unroll
                    for (int q = 0; q < 4; q++) {
                        int idx = g_csrsrc[e + q];
                        u[q] = *(const uint2*)(xb + (size_t)idx * (F / 2));
                    }
                    #pragma unroll
                    for (int q = 0; q < 4; q++) {
                        acc.x += BF_LO(u[q].x); acc.y += BF_HI(u[q].x);
                        acc.z += BF_LO(u[q].y); acc.w += BF_HI(u[q].y);
                    }
                }
                for (; e < end; e++) {
                    uint2 u0 = *(const uint2*)(xb + (size_t)g_csrsrc[e] * (F / 2));
                    acc.x += BF_LO(u0.x); acc.y += BF_HI(u0.x);
                    acc.z += BF_LO(u0.y); acc.w += BF_HI(u0.y);
                }
                float dn = g_dstnorm[m];
                acc.x *= dn; acc.y *= dn; acc.z *= dn; acc.w *= dn;
            }
            shAb[ml * AP + lane * 2]     = pack_bf2(acc.x, acc.y);
            shAb[ml * AP + lane * 2 + 1] = pack_bf2(acc.z, acc.w);
        }
        __syncthreads();

        // --- GEMM: warp w owns cols [16w, 16w+16); 8 k-iterations of k16 MMA ---
        int nb0 = w * 16, nb1 = nb0 + 8;
        float2 bb0 = *(float2*)(shB + nb0 + 2 * tig);
        float2 bb1 = *(float2*)(shB + nb1 + 2 * tig);
        float c00 = bb0.x, c01 = bb0.y, c02 = bb0.x, c03 = bb0.y;
        float c10 = bb1.x, c11 = bb1.y, c12 = bb1.x, c13 = bb1.y;

        const unsigned* A0 = shAb + g * AP;
        const unsigned* A1 = shAb + (g + 8) * AP;
        const unsigned* B0 = shWb + (nb0 + g) * AP;
        const unsigned* B1 = shWb + (nb1 + g) * AP;
        #pragma unroll
        for (int kt = 0; kt < 8; kt++) {
            int j0 = kt * 8;
            unsigned a0 = A0[j0 + tig],     a1 = A1[j0 + tig];
            unsigned a2 = A0[j0 + 4 + tig], a3 = A1[j0 + 4 + tig];
            mma_bf16(c00, c01, c02, c03, a0, a1, a2, a3, B0[j0 + tig], B0[j0 + 4 + tig]);
            mma_bf16(c10, c11, c12, c13, a0, a1, a2, a3, B1[j0 + tig], B1[j0 + 4 + tig]);
        }

        // epilogue: relu + src_norm fold, bf16-packed store
        int m0 = base + g, m1 = base + g + 8;
        if (m0 < n) {
            float sn = g_srcnorm[m0];
            unsigned* o = out + (size_t)m0 * (F / 2);
            o[nb0 / 2 + tig] = pack_bf2(fmaxf(c00, 0.f) * sn, fmaxf(c01, 0.f) * sn);
            o[nb1 / 2 + tig] = pack_bf2(fmaxf(c10, 0.f) * sn, fmaxf(c11, 0.f) * sn);
        }
        if (m1 < n) {
            float sn = g_srcnorm[m1];
            unsigned* o = out + (size_t)m1 * (F / 2);
            o[nb0 / 2 + tig] = pack_bf2(fmaxf(c02, 0.f) * sn, fmaxf(c03, 0.f) * sn);
            o[nb1 / 2 + tig] = pack_bf2(fmaxf(c12, 0.f) * sn, fmaxf(c13, 0.f) * sn);
        }
        __syncthreads();
    }
}

// ---------------- y = x2s @ W3 via bf16 MMA (project BEFORE last SpMM) ----------------
__global__ void __launch_bounds__(256) k_pre3(
    const unsigned* __restrict__ x,       // bf16-packed, row stride 64 uints
    const float* __restrict__ W3,         // [F][64] row-major fp32
    unsigned* __restrict__ y, int n, int numTiles)
{
    __shared__ unsigned shWb[64 * AP];    // 17408 B
    __shared__ unsigned shXb[16 * AP];    // 4352 B
    int tid = threadIdx.x;
    for (int i = tid; i < 64 * (F / 2); i += 256) {
        int k2 = i >> 6, nn = i & 63;
        shWb[nn * AP + k2] = pack_bf2(W3[(2 * k2) * 64 + nn], W3[(2 * k2 + 1) * 64 + nn]);
    }
    __syncthreads();

    int w = tid >> 5, lane = tid & 31;
    int g = lane >> 2, tig = lane & 3;

    for (int t = blockIdx.x; t < numTiles; t += gridDim.x) {
        int base = t * 16;
        {   // load 16 rows x 64 uints (uint4 per thread)
            int r = tid >> 4, q = tid & 15;
            int node = base + r;
            uint4 v = (node < n) ? ((const uint4*)(x + (size_t)node * 64))[q]
                                 : make_uint4(0u, 0u, 0u, 0u);
            unsigned* p = shXb + r * AP + q * 4;
            p[0] = v.x; p[1] = v.y; p[2] = v.z; p[3] = v.w;
        }
        __syncthreads();

        int nb = w * 8;
        float c0 = 0.f, c1 = 0.f, c2 = 0.f, c3 = 0.f;
        const unsigned* A0 = shXb + g * AP;
        const unsigned* A1 = shXb + (g + 8) * AP;
        const unsigned* B0 = shWb + (nb + g) * AP;
        #pragma unroll
        for (int kt = 0; kt < 8; kt++) {
            int j0 = kt * 8;
            mma_bf16(c0, c1, c2, c3,
                     A0[j0 + tig], A1[j0 + tig], A0[j0 + 4 + tig], A1[j0 + 4 + tig],
                     B0[j0 + tig], B0[j0 + 4 + tig]);
        }
        int m0 = base + g, m1 = base + g + 8;
        if (m0 < n) y[(size_t)m0 * 32 + nb / 2 + tig] = pack_bf2(c0, c1);
        if (m1 < n) y[(size_t)m1 * 32 + nb / 2 + tig] = pack_bf2(c2, c3);
        __syncthreads();
    }
}

// ---------------- layer 3 aggregation (bf16, width 64) + bias + relu + head + sigmoid ------
__global__ void k_layer3(
    const unsigned* __restrict__ y, const float* __restrict__ b3,
    const float* __restrict__ Wp, const float* __restrict__ bp,
    float* __restrict__ out, int n)
{
    int gw = (blockIdx.x * blockDim.x + threadIdx.x) >> 5;   // warp per node
    int lane = threadIdx.x & 31;
    if (gw >= n) return;
    int m = gw;
    int e = g_offsets[m], end = g_offsets[m + 1];
    float2 acc = make_float2(0.f, 0.f);
    const unsigned* yb = y + lane;   // 1 uint = 2 bf16; row stride 32
    for (; e + 8 <= end; e += 8) {
        unsigned u[8];
        #pragma unroll
        for (int q = 0; q < 8; q++) u[q] = yb[(size_t)g_csrsrc[e + q] * 32];
        #pragma unroll
        for (int q = 0; q < 8; q++) { acc.x += BF_LO(u[q]); acc.y += BF_HI(u[q]); }
    }
    for (; e + 4 <= end; e += 4) {
        unsigned u[4];
        #pragma unroll
        for (int q = 0; q < 4; q++) u[q] = yb[(size_t)g_csrsrc[e + q] * 32];
        #pragma unroll
        for (int q = 0; q < 4; q++) { acc.x += BF_LO(u[q]); acc.y += BF_HI(u[q]); }
    }
    for (; e < end; e++) {
        unsigned u0 = yb[(size_t)g_csrsrc[e] * 32];
        acc.x += BF_LO(u0); acc.y += BF_HI(u0);
    }
    float dn = g_dstnorm[m];
    float2 bb = *(const float2*)(b3 + lane * 2);
    float hx = fmaxf(acc.x * dn + bb.x, 0.f);
    float hy = fmaxf(acc.y * dn + bb.y, 0.f);
    float2 wp = *(const float2*)(Wp + lane * 2);
    float p = hx * wp.x + hy * wp.y;
    #pragma unroll
    for (int o = 16; o; o >>= 1) p += __shfl_xor_sync(0xffffffffu, p, o);
    if (lane == 0) {
        float l = p + bp[0];
        out[m] = 1.f / (1.f + __expf(-l));
    }
}

// ---------------- launch ----------------
extern "C" void kernel_launch(void* const* d_in, const int* in_sizes, int n_in,
                              void* d_out, int out_size)
{
    const float* feats = (const float*)d_in[0];
    const int*   src   = (const int*)d_in[1];
    const int*   dst   = (const int*)d_in[2];
    // d_in[3] = edge_types (unused)
    const float* W1 = (const float*)d_in[4];
    const float* b1 = (const float*)d_in[5];
    const float* W2 = (const float*)d_in[6];
    const float* b2 = (const float*)d_in[7];
    const float* W3 = (const float*)d_in[8];
    const float* b3 = (const float*)d_in[9];
    const float* Wp = (const float*)d_in[10];
    const float* bp = (const float*)d_in[11];
    float* out = (float*)d_out;

    int n = in_sizes[0] / F;   // 50000
    int e = in_sizes[1];       // 800000

    unsigned *h0, *h1, *hy;
    cudaGetSymbolAddress((void**)&h0, g_h0);
    cudaGetSymbolAddress((void**)&h1, g_h1);
    cudaGetSymbolAddress((void**)&hy, g_hy);

    int nb = (n + 1023) / 1024;
    int tiles = (n + 15) / 16;

    k_zero   <<<(n + 255) / 256, 256>>>(n);
    k_deg    <<<(e + 255) / 256, 256>>>(src, dst, e);
    k_scan1  <<<nb, 1024>>>(n);
    k_scan2  <<<1, 32>>>(nb);
    k_scan3  <<<(n + 255) / 256, 256>>>(n, e);
    k_scatter<<<(e + 255) / 256, 256>>>(src, dst, e);
    k_scale0 <<<(n * (F / 4) + 255) / 256, 256>>>(feats, n);

    // persistent grids sized to residency: 5 blocks/SM * 148 = 740; pre3: 8/SM -> 1184
    k_layer128<<<740, 256>>>(h0, W1, b1, h1, n, tiles);
    k_layer128<<<740, 256>>>(h1, W2, b2, h0, n, tiles);
    k_pre3    <<<1184, 256>>>(h0, W3, hy, n, tiles);
    k_layer3  <<<(n * 32 + 255) / 256, 256>>>(hy, b3, Wp, bp, out, n);
}

// round 5
// speedup vs baseline: 2.0904x; 1.0290x over previous
#include <cuda_runtime.h>
#include <math.h>

#define NN 50000
#define NE 800000
#define F  128
#define AP 68   // padded row stride (uints) for bf16x2 smem tiles: banks 4g+tig, conflict-free

// ---------------- scratch (device globals; no allocation allowed) ----------------
__device__ int   g_deg[2 * NN];          // [0,NN) = outdeg, [NN,2NN) = indeg
__device__ __align__(16) float g_srcnorm[NN];
__device__ __align__(16) float g_dstnorm[NN];
__device__ int   g_offsets[NN + 1];
__device__ int   g_cursor[NN];
__device__ int   g_csrsrc[NE];
__device__ int   g_blksums[64];
__device__ int   g_blkoffs[64];
// bf16-packed feature buffers (2 vals per uint)
__device__ __align__(16) unsigned g_h0[(size_t)NN * F / 2];
__device__ __align__(16) unsigned g_h1[(size_t)NN * F / 2];
__device__ __align__(16) unsigned g_hy[(size_t)NN * 64 / 2];

// ---------------- helpers ----------------
__device__ __forceinline__ unsigned pack_bf2(float lo, float hi) {
    unsigned r;
    asm("cvt.rn.bf16x2.f32 %0, %1, %2;" : "=r"(r) : "f"(hi), "f"(lo));
    return r;
}
#define BF_LO(u) __uint_as_float((u) << 16)
#define BF_HI(u) __uint_as_float((u) & 0xffff0000u)

__device__ __forceinline__ void mma_bf16(
    float& c0, float& c1, float& c2, float& c3,
    unsigned a0, unsigned a1, unsigned a2, unsigned a3,
    unsigned b0, unsigned b1)
{
    asm("mma.sync.aligned.m16n8k16.row.col.f32.bf16.bf16.f32 "
        "{%0,%1,%2,%3},{%4,%5,%6,%7},{%8,%9},{%0,%1,%2,%3};"
        : "+f"(c0), "+f"(c1), "+f"(c2), "+f"(c3)
        : "r"(a0), "r"(a1), "r"(a2), "r"(a3), "r"(b0), "r"(b1));
}

__device__ __forceinline__ int warp_incl_scan(int s, int lane) {
    #pragma unroll
    for (int o = 1; o < 32; o <<= 1) {
        int t = __shfl_up_sync(0xffffffffu, s, o);
        if (lane >= o) s += t;
    }
    return s;
}

// ---------------- preprocessing ----------------
__global__ void k_deg(const int* __restrict__ src, const int* __restrict__ dst, int e) {
    int i = blockIdx.x * blockDim.x + threadIdx.x;
    if (i < e) {
        atomicAdd(&g_deg[src[i]], 1);
        atomicAdd(&g_deg[NN + dst[i]], 1);
    }
}

// per-1024-block exclusive scan of indeg via warp shuffles
__global__ void k_scan1(int n) {
    __shared__ int warpsum[32];
    int tid = threadIdx.x;
    int i = blockIdx.x * 1024 + tid;
    int lane = tid & 31, wid = tid >> 5;
    int v = (i < n) ? g_deg[NN + i] : 0;
    int s = warp_incl_scan(v, lane);
    if (lane == 31) warpsum[wid] = s;
    __syncthreads();
    if (wid == 0) warpsum[lane] = warp_incl_scan(warpsum[lane], lane);
    __syncthreads();
    int incl = s + (wid > 0 ? warpsum[wid - 1] : 0);
    if (i < n) g_offsets[i] = incl - v;
    if (tid == 1023) g_blksums[blockIdx.x] = incl;
}

// 1-warp scan over block sums (nb <= 64)
__global__ void k_scan2(int nb) {
    int lane = threadIdx.x;
    int acc = 0;
    for (int b = 0; b < nb; b += 32) {
        int v = (b + lane < nb) ? g_blksums[b + lane] : 0;
        int s = warp_incl_scan(v, lane);
        if (b + lane < nb) g_blkoffs[b + lane] = acc + s - v;
        acc += __shfl_sync(0xffffffffu, s, 31);
    }
}

// finish scan + compute norms (fused)
__global__ void k_scan3(int n, int e) {
    int i = blockIdx.x * blockDim.x + threadIdx.x;
    if (i < n) {
        int o = g_offsets[i] + g_blkoffs[i >> 10];
        g_offsets[i] = o;
        g_cursor[i] = o;
        int od = g_deg[i];
        int id = g_deg[NN + i];
        g_srcnorm[i] = od > 0 ? rsqrtf((float)od) : 0.f;
        g_dstnorm[i] = id > 0 ? rsqrtf((float)id) : 0.f;
    }
    if (i == 0) g_offsets[n] = e;
}

// fused: CSR scatter (blocks [0, eb)) + h0 = bf16(features * src_norm) (blocks [eb, ...))
__global__ void k_scatter_scale(
    const int* __restrict__ src, const int* __restrict__ dst,
    const float* __restrict__ feats, int e, int n, int eb)
{
    int b = blockIdx.x;
    if (b < eb) {
        int i = b * 256 + threadIdx.x;
        if (i < e) {
            int d = dst[i];
            int pos = atomicAdd(&g_cursor[d], 1);
            g_csrsrc[pos] = src[i];
        }
    } else {
        int i = (b - eb) * 256 + threadIdx.x;   // over n * (F/4)
        if (i < n * (F / 4)) {
            int row = i >> 5;
            float4 v = ((const float4*)feats)[i];
            float s = g_srcnorm[row];
            uint2 o;
            o.x = pack_bf2(v.x * s, v.y * s);
            o.y = pack_bf2(v.z * s, v.w * s);
            ((uint2*)g_h0)[i] = o;
        }
    }
}

// ---------------- fused conv layer: bf16 gather-SpMM + bf16 MMA GEMM + relu + src_norm fold ----
__global__ void __launch_bounds__(256, 5) k_layer128(
    const unsigned* __restrict__ xs,      // bf16-packed, row stride F/2 uints
    const float* __restrict__ W,          // [F][F] row-major fp32
    const float* __restrict__ bias,
    unsigned* __restrict__ out,           // bf16-packed output
    int n, int numTiles)
{
    __shared__ unsigned shWb[F * AP];     // [n][k/2] bf16x2  (34816 B)
    __shared__ unsigned shAb[16 * AP];    // aggregated tile, bf16x2 (4352 B)
    __shared__ float    shB[F];           // bias

    int tid = threadIdx.x;
    for (int i = tid; i < F * (F / 2); i += 256) {
        int k2 = i >> 7, nn = i & (F - 1);
        shWb[nn * AP + k2] = pack_bf2(W[(2 * k2) * F + nn], W[(2 * k2 + 1) * F + nn]);
    }
    if (tid < F / 4) ((float4*)shB)[tid] = ((const float4*)bias)[tid];
    __syncthreads();

    int w = tid >> 5, lane = tid & 31;
    int g = lane >> 2, tig = lane & 3;

    for (int t = blockIdx.x; t < numTiles; t += gridDim.x) {
        int base = t * 16;

        #pragma unroll
        for (int s2 = 0; s2 < 2; s2++) {
            int ml = w + s2 * 8;
            int m = base + ml;
            float4 acc = make_float4(0.f, 0.f, 0.f, 0.f);
            if (m < n) {
                int e = g_offsets[m], end = g_offsets[m + 1];
                const unsigned* xb = xs + lane * 2;
                for (; e + 8 <= end; e += 8) {
                    uint2 u[8];
                    #pragma unroll
                    for (int q = 0; q < 8; q++) {
                        int idx = g_csrsrc[e + q];
                        u[q] = *(const uint2*)(xb + (size_t)idx * (F / 2));
                    }
                    #pragma unroll
                    for (int q = 0; q < 8; q++) {
                        acc.x += BF_LO(u[q].x); acc.y += BF_HI(u[q].x);
                        acc.z += BF_LO(u[q].y); acc.w += BF_HI(u[q].y);
                    }
                }
                for (; e + 4 <= end; e += 4) {
                    uint2 u[4];
                    #pragma unroll
                    for (int q = 0; q < 4; q++) {
                        int idx = g_csrsrc[e + q];
                        u[q] = *(const uint2*)(xb + (size_t)idx * (F / 2));
                    }
                    #pragma unroll
                    for (int q = 0; q < 4; q++) {
                        acc.x += BF_LO(u[q].x); acc.y += BF_HI(u[q].x);
                        acc.z += BF_LO(u[q].y); acc.w += BF_HI(u[q].y);
                    }
                }
                for (; e < end; e++) {
                    uint2 u0 = *(const uint2*)(xb + (size_t)g_csrsrc[e] * (F / 2));
                    acc.x += BF_LO(u0.x); acc.y += BF_HI(u0.x);
                    acc.z += BF_LO(u0.y); acc.w += BF_HI(u0.y);
                }
                float dn = g_dstnorm[m];
                acc.x *= dn; acc.y *= dn; acc.z *= dn; acc.w *= dn;
            }
            shAb[ml * AP + lane * 2]     = pack_bf2(acc.x, acc.y);
            shAb[ml * AP + lane * 2 + 1] = pack_bf2(acc.z, acc.w);
        }
        __syncthreads();

        int nb0 = w * 16, nb1 = nb0 + 8;
        float2 bb0 = *(float2*)(shB + nb0 + 2 * tig);
        float2 bb1 = *(float2*)(shB + nb1 + 2 * tig);
        float c00 = bb0.x, c01 = bb0.y, c02 = bb0.x, c03 = bb0.y;
        float c10 = bb1.x, c11 = bb1.y, c12 = bb1.x, c13 = bb1.y;

        const unsigned* A0 = shAb + g * AP;
        const unsigned* A1 = shAb + (g + 8) * AP;
        const unsigned* B0 = shWb + (nb0 + g) * AP;
        const unsigned* B1 = shWb + (nb1 + g) * AP;
        #pragma unroll
        for (int kt = 0; kt < 8; kt++) {
            int j0 = kt * 8;
            unsigned a0 = A0[j0 + tig],     a1 = A1[j0 + tig];
            unsigned a2 = A0[j0 + 4 + tig], a3 = A1[j0 + 4 + tig];
            mma_bf16(c00, c01, c02, c03, a0, a1, a2, a3, B0[j0 + tig], B0[j0 + 4 + tig]);
            mma_bf16(c10, c11, c12, c13, a0, a1, a2, a3, B1[j0 + tig], B1[j0 + 4 + tig]);
        }

        int m0 = base + g, m1 = base + g + 8;
        if (m0 < n) {
            float sn = g_srcnorm[m0];
            unsigned* o = out + (size_t)m0 * (F / 2);
            o[nb0 / 2 + tig] = pack_bf2(fmaxf(c00, 0.f) * sn, fmaxf(c01, 0.f) * sn);
            o[nb1 / 2 + tig] = pack_bf2(fmaxf(c10, 0.f) * sn, fmaxf(c11, 0.f) * sn);
        }
        if (m1 < n) {
            float sn = g_srcnorm[m1];
            unsigned* o = out + (size_t)m1 * (F / 2);
            o[nb0 / 2 + tig] = pack_bf2(fmaxf(c02, 0.f) * sn, fmaxf(c03, 0.f) * sn);
            o[nb1 / 2 + tig] = pack_bf2(fmaxf(c12, 0.f) * sn, fmaxf(c13, 0.f) * sn);
        }
        __syncthreads();
    }
}

// ---------------- y = x2s @ W3 via bf16 MMA (project BEFORE last SpMM) ----------------
__global__ void __launch_bounds__(256) k_pre3(
    const unsigned* __restrict__ x,       // bf16-packed, row stride 64 uints
    const float* __restrict__ W3,         // [F][64] row-major fp32
    unsigned* __restrict__ y, int n, int numTiles)
{
    __shared__ unsigned shWb[64 * AP];
    __shared__ unsigned shXb[16 * AP];
    int tid = threadIdx.x;
    for (int i = tid; i < 64 * (F / 2); i += 256) {
        int k2 = i >> 6, nn = i & 63;
        shWb[nn * AP + k2] = pack_bf2(W3[(2 * k2) * 64 + nn], W3[(2 * k2 + 1) * 64 + nn]);
    }
    __syncthreads();

    int w = tid >> 5, lane = tid & 31;
    int g = lane >> 2, tig = lane & 3;

    for (int t = blockIdx.x; t < numTiles; t += gridDim.x) {
        int base = t * 16;
        {
            int r = tid >> 4, q = tid & 15;
            int node = base + r;
            uint4 v = (node < n) ? ((const uint4*)(x + (size_t)node * 64))[q]
                                 : make_uint4(0u, 0u, 0u, 0u);
            unsigned* p = shXb + r * AP + q * 4;
            p[0] = v.x; p[1] = v.y; p[2] = v.z; p[3] = v.w;
        }
        __syncthreads();

        int nb = w * 8;
        float c0 = 0.f, c1 = 0.f, c2 = 0.f, c3 = 0.f;
        const unsigned* A0 = shXb + g * AP;
        const unsigned* A1 = shXb + (g + 8) * AP;
        const unsigned* B0 = shWb + (nb + g) * AP;
        #pragma unroll
        for (int kt = 0; kt < 8; kt++) {
            int j0 = kt * 8;
            mma_bf16(c0, c1, c2, c3,
                     A0[j0 + tig], A1[j0 + tig], A0[j0 + 4 + tig], A1[j0 + 4 + tig],
                     B0[j0 + tig], B0[j0 + 4 + tig]);
        }
        int m0 = base + g, m1 = base + g + 8;
        if (m0 < n) y[(size_t)m0 * 32 + nb / 2 + tig] = pack_bf2(c0, c1);
        if (m1 < n) y[(size_t)m1 * 32 + nb / 2 + tig] = pack_bf2(c2, c3);
        __syncthreads();
    }
}

// ---------------- layer 3 aggregation (bf16, width 64) + bias + relu + head + sigmoid ------
__global__ void k_layer3(
    const unsigned* __restrict__ y, const float* __restrict__ b3,
    const float* __restrict__ Wp, const float* __restrict__ bp,
    float* __restrict__ out, int n)
{
    int gw = (blockIdx.x * blockDim.x + threadIdx.x) >> 5;
    int lane = threadIdx.x & 31;
    if (gw >= n) return;
    int m = gw;
    int e = g_offsets[m], end = g_offsets[m + 1];
    float2 acc = make_float2(0.f, 0.f);
    const unsigned* yb = y + lane;
    for (; e + 8 <= end; e += 8) {
        unsigned u[8];
        #pragma unroll
        for (int q = 0; q < 8; q++) u[q] = yb[(size_t)g_csrsrc[e + q] * 32];
        #pragma unroll
        for (int q = 0; q < 8; q++) { acc.x += BF_LO(u[q]); acc.y += BF_HI(u[q]); }
    }
    for (; e + 4 <= end; e += 4) {
        unsigned u[4];
        #pragma unroll
        for (int q = 0; q < 4; q++) u[q] = yb[(size_t)g_csrsrc[e + q] * 32];
        #pragma unroll
        for (int q = 0; q < 4; q++) { acc.x += BF_LO(u[q]); acc.y += BF_HI(u[q]); }
    }
    for (; e < end; e++) {
        unsigned u0 = yb[(size_t)g_csrsrc[e] * 32];
        acc.x += BF_LO(u0); acc.y += BF_HI(u0);
    }
    float dn = g_dstnorm[m];
    float2 bb = *(const float2*)(b3 + lane * 2);
    float hx = fmaxf(acc.x * dn + bb.x, 0.f);
    float hy = fmaxf(acc.y * dn + bb.y, 0.f);
    float2 wp = *(const float2*)(Wp + lane * 2);
    float p = hx * wp.x + hy * wp.y;
    #pragma unroll
    for (int o = 16; o; o >>= 1) p += __shfl_xor_sync(0xffffffffu, p, o);
    if (lane == 0) {
        float l = p + bp[0];
        out[m] = 1.f / (1.f + __expf(-l));
    }
}

// ---------------- launch ----------------
extern "C" void kernel_launch(void* const* d_in, const int* in_sizes, int n_in,
                              void* d_out, int out_size)
{
    const float* feats = (const float*)d_in[0];
    const int*   src   = (const int*)d_in[1];
    const int*   dst   = (const int*)d_in[2];
    // d_in[3] = edge_types (unused)
    const float* W1 = (const float*)d_in[4];
    const float* b1 = (const float*)d_in[5];
    const float* W2 = (const float*)d_in[6];
    const float* b2 = (const float*)d_in[7];
    const float* W3 = (const float*)d_in[8];
    const float* b3 = (const float*)d_in[9];
    const float* Wp = (const float*)d_in[10];
    const float* bp = (const float*)d_in[11];
    float* out = (float*)d_out;

    int n = in_sizes[0] / F;   // 50000
    int e = in_sizes[1];       // 800000

    unsigned *h0, *h1, *hy;
    int* degp;
    cudaGetSymbolAddress((void**)&h0, g_h0);
    cudaGetSymbolAddress((void**)&h1, g_h1);
    cudaGetSymbolAddress((void**)&hy, g_hy);
    cudaGetSymbolAddress((void**)&degp, g_deg);

    int nb = (n + 1023) / 1024;
    int tiles = (n + 15) / 16;
    int eb = (e + 255) / 256;                 // scatter blocks
    int sb = (n * (F / 4) + 255) / 256;       // scale blocks

    cudaMemsetAsync(degp, 0, sizeof(int) * 2 * NN);
    k_deg          <<<(e + 255) / 256, 256>>>(src, dst, e);
    k_scan1        <<<nb, 1024>>>(n);
    k_scan2        <<<1, 32>>>(nb);
    k_scan3        <<<(n + 255) / 256, 256>>>(n, e);
    k_scatter_scale<<<eb + sb, 256>>>(src, dst, feats, e, n, eb);

    k_layer128<<<740, 256>>>(h0, W1, b1, h1, n, tiles);
    k_layer128<<<740, 256>>>(h1, W2, b2, h0, n, tiles);
    k_pre3    <<<1184, 256>>>(h0, W3, hy, n, tiles);
    k_layer3  <<<(n * 32 + 255) / 256, 256>>>(hy, b3, Wp, bp, out, n);
}